// round 3
// baseline (speedup 1.0000x reference)
#include <cuda_runtime.h>
#include <math.h>

// Decoder free-run greedy decode. B=1024, T=64, V=256, LAT=256, H=512, L=2.
// Multi-launch design: 2 setup kernels + 64 steps x 3 kernels, all stream-
// ordered (graph-capturable, no grid barriers, no dynamic smem, no attrs).
//
// Per step t:
//   A: h0' = GRU0(h0, pre[b] + w_ih0_vocab_col[idx[b]])   (one-hot -> gather)
//   B: h1' = GRU1(h0', h1)
//   C: logits = h1' @ w_fc^T + b_fc ; argmax ; one-hot out ; idx update

#define NTHR 256
#define Bq   1024
#define Hq   512
#define TH3  1536
#define Vq   256
#define LATq 256
#define Tq   64

// ---------------- device scratch ------------------------------------------
__device__ float g_pre[Bq * TH3];          // latent part of gi0 (+b_ih0)
__device__ float g_wvT[Vq * TH3];          // w_ih0 vocab cols, [v][gate3H]
__device__ float g_wfcT[Hq * Vq];          // w_fc transposed [k][v]
__device__ float g_h0[2][Bq * Hq];
__device__ float g_h1[2][Bq * Hq];
__device__ int   g_idx[Bq];

__device__ __forceinline__ float sigmoidf_(float x) {
    return 1.0f / (1.0f + expf(-x));
}

// ---------------- init: zero state + build transposes ---------------------
__global__ void __launch_bounds__(NTHR) init_kernel(
    const float* __restrict__ w_ih0, const float* __restrict__ w_fc)
{
    const int gt = blockIdx.x * NTHR + threadIdx.x;    // 0..32767
    float4 z = make_float4(0.f, 0.f, 0.f, 0.f);
    #pragma unroll
    for (int q = 0; q < 4; q++) {                      // zero parity-0 h
        int i = gt + 32768 * q;                        // 131072 float4 each
        reinterpret_cast<float4*>(g_h0[0])[i] = z;
        reinterpret_cast<float4*>(g_h1[0])[i] = z;
    }
    if (gt < Bq) g_idx[gt] = -1;
    #pragma unroll
    for (int q = 0; q < 12; q++) {                     // w_ih0 vocab transpose
        int i = gt + 32768 * q;                        // 393216 floats
        int v = i / TH3, g = i - v * TH3;
        g_wvT[i] = w_ih0[g * 512 + 256 + v];
    }
    #pragma unroll
    for (int q = 0; q < 4; q++) {                      // w_fc transpose [k][v]
        int i = gt + 32768 * q;                        // 131072 floats
        int k = i >> 8, v = i & 255;
        g_wfcT[i] = w_fc[v * 512 + k];
    }
}

// ---------------- tiled GEMM accumulate (K-panel 32, static smem) ---------
// acc[8][6] += A[rbase..rbase+64, 0..ktot) @ Wslice^T
// Wslice cols (192) = gate*512 + hs*64 + c.  thread (tx,ty): rows 8ty+i,
// cols 32j+tx.
#define SWP 33
__device__ __forceinline__ void gemm32(
    float acc[8][6],
    const float* __restrict__ A, int apitch, int rbase, int ktot,
    const float* __restrict__ W, int wpitch, int hs,
    float* sW, float* sH, int tid)
{
    const int tx = tid & 31;
    const int ty = tid >> 5;
    for (int k0 = 0; k0 < ktot; k0 += 32) {
        __syncthreads();
        // W panel: 192 rows x 32 k = 1536 float4
        #pragma unroll
        for (int q = 0; q < 6; q++) {
            int f4  = tid + 256 * q;
            int row = f4 >> 3;
            int kq  = f4 & 7;
            int gate = row >> 6;
            int c    = row & 63;
            int g    = gate * 512 + hs * 64 + c;
            float4 v = *reinterpret_cast<const float4*>(
                &W[(size_t)g * wpitch + k0 + 4 * kq]);
            float* d = &sW[row * SWP + 4 * kq];
            d[0] = v.x; d[1] = v.y; d[2] = v.z; d[3] = v.w;
        }
        // A panel: 64 rows x 32 k = 512 float4
        #pragma unroll
        for (int q = 0; q < 2; q++) {
            int f4 = tid + 256 * q;
            int b  = f4 >> 3;
            int kq = f4 & 7;
            float4 v = *reinterpret_cast<const float4*>(
                &A[(size_t)(rbase + b) * apitch + k0 + 4 * kq]);
            *reinterpret_cast<float4*>(&sH[b * 32 + 4 * kq]) = v;
        }
        __syncthreads();
        #pragma unroll 8
        for (int k = 0; k < 32; k++) {
            float a[8], w[6];
            #pragma unroll
            for (int i = 0; i < 8; i++) a[i] = sH[(8 * ty + i) * 32 + k];
            #pragma unroll
            for (int j = 0; j < 6; j++) w[j] = sW[(32 * j + tx) * SWP + k];
            #pragma unroll
            for (int i = 0; i < 8; i++)
                #pragma unroll
                for (int j = 0; j < 6; j++)
                    acc[i][j] += a[i] * w[j];
        }
    }
}

// ---------------- pre: g_pre = latent @ w_ih0[:, :256]^T + b_ih0 ----------
__global__ void __launch_bounds__(NTHR) pre_kernel(
    const float* __restrict__ latent,
    const float* __restrict__ w_ih0, const float* __restrict__ b_ih0)
{
    __shared__ float sW[192 * SWP];
    __shared__ float sH[64 * 32];
    const int tid  = threadIdx.x;
    const int bb   = blockIdx.x;
    const int hs   = bb & 7;
    const int rbase = (bb >> 3) * 64;
    const int tx = tid & 31;
    const int ty = tid >> 5;

    float acc[8][6];
    #pragma unroll
    for (int i = 0; i < 8; i++)
        #pragma unroll
        for (int j = 0; j < 6; j++) acc[i][j] = 0.f;
    gemm32(acc, latent, LATq, rbase, LATq, w_ih0, 512, hs, sW, sH, tid);
    #pragma unroll
    for (int j = 0; j < 6; j++) {
        int cidx = 32 * j + tx;
        int gate = cidx >> 6;
        int c    = cidx & 63;
        int g    = gate * 512 + hs * 64 + c;
        float bi = b_ih0[g];
        #pragma unroll
        for (int i = 0; i < 8; i++) {
            int b = rbase + 8 * ty + i;
            g_pre[(size_t)b * TH3 + g] = acc[i][j] + bi;
        }
    }
}

// ---------------- stage A: layer-0 GRU ------------------------------------
__global__ void __launch_bounds__(NTHR) stepA_kernel(
    const float* __restrict__ w_hh0, const float* __restrict__ b_hh0, int t)
{
    __shared__ float sW[192 * SWP];
    __shared__ float sH[64 * 32];
    const int pr = t & 1, pw = 1 - pr;
    const int tid  = threadIdx.x;
    const int bb   = blockIdx.x;
    const int hs   = bb & 7;
    const int rbase = (bb >> 3) * 64;
    const int tx = tid & 31;
    const int ty = tid >> 5;

    float acc[8][6];
    #pragma unroll
    for (int i = 0; i < 8; i++)
        #pragma unroll
        for (int j = 0; j < 6; j++) acc[i][j] = 0.f;
    gemm32(acc, g_h0[pr], Hq, rbase, Hq, w_hh0, 512, hs, sW, sH, tid);

    #pragma unroll
    for (int jj = 0; jj < 2; jj++) {
        int c  = tx + 32 * jj;
        int gR = 0    + hs * 64 + c;
        int gZ = 512  + hs * 64 + c;
        int gN = 1024 + hs * 64 + c;
        float bhR = b_hh0[gR], bhZ = b_hh0[gZ], bhN = b_hh0[gN];
        #pragma unroll
        for (int i = 0; i < 8; i++) {
            int b  = rbase + 8 * ty + i;
            int ix = g_idx[b];
            float ir  = g_pre[(size_t)b * TH3 + gR];
            float iz  = g_pre[(size_t)b * TH3 + gZ];
            float in_ = g_pre[(size_t)b * TH3 + gN];
            if (ix >= 0) {
                ir  += g_wvT[(size_t)ix * TH3 + gR];
                iz  += g_wvT[(size_t)ix * TH3 + gZ];
                in_ += g_wvT[(size_t)ix * TH3 + gN];
            }
            float r = sigmoidf_(ir  + acc[i][jj]     + bhR);
            float z = sigmoidf_(iz  + acc[i][jj + 2] + bhZ);
            float n = tanhf   (in_ + r * (acc[i][jj + 4] + bhN));
            float hold = g_h0[pr][(size_t)b * Hq + hs * 64 + c];
            g_h0[pw][(size_t)b * Hq + hs * 64 + c] = (1.f - z) * n + z * hold;
        }
    }
}

// ---------------- stage B: layer-1 GRU ------------------------------------
__global__ void __launch_bounds__(NTHR) stepB_kernel(
    const float* __restrict__ w_ih1, const float* __restrict__ w_hh1,
    const float* __restrict__ b_ih1, const float* __restrict__ b_hh1, int t)
{
    __shared__ float sW[192 * SWP];
    __shared__ float sH[64 * 32];
    const int pr = t & 1, pw = 1 - pr;
    const int tid  = threadIdx.x;
    const int bb   = blockIdx.x;
    const int hs   = bb & 7;
    const int rbase = (bb >> 3) * 64;
    const int tx = tid & 31;
    const int ty = tid >> 5;

    float ai[8][6], ah[8][6];
    #pragma unroll
    for (int i = 0; i < 8; i++)
        #pragma unroll
        for (int j = 0; j < 6; j++) { ai[i][j] = 0.f; ah[i][j] = 0.f; }
    gemm32(ai, g_h0[pw], Hq, rbase, Hq, w_ih1, 512, hs, sW, sH, tid);
    gemm32(ah, g_h1[pr], Hq, rbase, Hq, w_hh1, 512, hs, sW, sH, tid);

    #pragma unroll
    for (int jj = 0; jj < 2; jj++) {
        int c  = tx + 32 * jj;
        int gR = 0    + hs * 64 + c;
        int gZ = 512  + hs * 64 + c;
        int gN = 1024 + hs * 64 + c;
        float biR = b_ih1[gR], biZ = b_ih1[gZ], biN = b_ih1[gN];
        float bhR = b_hh1[gR], bhZ = b_hh1[gZ], bhN = b_hh1[gN];
        #pragma unroll
        for (int i = 0; i < 8; i++) {
            int b = rbase + 8 * ty + i;
            float r = sigmoidf_(ai[i][jj]     + biR + ah[i][jj]     + bhR);
            float z = sigmoidf_(ai[i][jj + 2] + biZ + ah[i][jj + 2] + bhZ);
            float n = tanhf   (ai[i][jj + 4] + biN + r * (ah[i][jj + 4] + bhN));
            float hold = g_h1[pr][(size_t)b * Hq + hs * 64 + c];
            g_h1[pw][(size_t)b * Hq + hs * 64 + c] = (1.f - z) * n + z * hold;
        }
    }
}

// ---------------- stage C: logits + argmax + one-hot ----------------------
__global__ void __launch_bounds__(NTHR) stepC_kernel(
    const float* __restrict__ b_fc, float* __restrict__ out, int t)
{
    __shared__ float sHL[8 * Hq];     // 8 rows of h1
    __shared__ float sLOG[8 * Vq];
    __shared__ int   sIDX[8];
    const int pw = 1 - (t & 1);
    const int tid = threadIdx.x;
    const int tx  = tid & 31;
    const int ty  = tid >> 5;
    const int rb  = blockIdx.x * 8;

    #pragma unroll
    for (int q = 0; q < 4; q++) {
        int f4 = tid + 256 * q;          // 1024 float4
        int r  = f4 >> 7;
        int kq = f4 & 127;
        float4 v = *reinterpret_cast<const float4*>(
            &g_h1[pw][(size_t)(rb + r) * Hq + 4 * kq]);
        *reinterpret_cast<float4*>(&sHL[r * Hq + 4 * kq]) = v;
    }
    __syncthreads();

    float acc[8];
    #pragma unroll
    for (int r = 0; r < 8; r++) acc[r] = 0.f;
    #pragma unroll 8
    for (int k = 0; k < Hq; k++) {
        float wv = g_wfcT[k * Vq + tid];
        #pragma unroll
        for (int r = 0; r < 8; r++) acc[r] += sHL[r * Hq + k] * wv;
    }
    float bf = b_fc[tid];
    #pragma unroll
    for (int r = 0; r < 8; r++) sLOG[r * Vq + tid] = acc[r] + bf;
    __syncthreads();

    {   // warp ty reduces row ty, first-max tie-break (matches jnp.argmax)
        int row = ty;
        float bv = -3.4e38f;
        int   bi = 0;
        #pragma unroll
        for (int m = 0; m < 8; m++) {
            int idx = tx + 32 * m;
            float v = sLOG[row * Vq + idx];
            if (v > bv) { bv = v; bi = idx; }
        }
        #pragma unroll
        for (int off = 16; off > 0; off >>= 1) {
            float ov = __shfl_down_sync(0xffffffffu, bv, off);
            int   oi = __shfl_down_sync(0xffffffffu, bi, off);
            if (ov > bv || (ov == bv && oi < bi)) { bv = ov; bi = oi; }
        }
        if (tx == 0) sIDX[row] = bi;
    }
    __syncthreads();
    #pragma unroll
    for (int r = 0; r < 8; r++) {
        out[(size_t)(rb + r) * (Tq * Vq) + t * Vq + tid] =
            (tid == sIDX[r]) ? 1.0f : 0.0f;
    }
    if (tid < 8) g_idx[rb + tid] = sIDX[tid];
}

// ---------------- launch ---------------------------------------------------
extern "C" void kernel_launch(void* const* d_in, const int* in_sizes, int n_in,
                              void* d_out, int out_size)
{
    const float* latent = (const float*)d_in[0];
    // d_in[1] enthalpy: unused on freerun path
    const float* w_ih0  = (const float*)d_in[2];
    const float* w_hh0  = (const float*)d_in[3];
    const float* b_ih0  = (const float*)d_in[4];
    const float* b_hh0  = (const float*)d_in[5];
    const float* w_ih1  = (const float*)d_in[6];
    const float* w_hh1  = (const float*)d_in[7];
    const float* b_ih1  = (const float*)d_in[8];
    const float* b_hh1  = (const float*)d_in[9];
    const float* w_fc   = (const float*)d_in[10];
    const float* b_fc   = (const float*)d_in[11];
    float* out = (float*)d_out;

    init_kernel<<<128, NTHR>>>(w_ih0, w_fc);
    pre_kernel<<<128, NTHR>>>(latent, w_ih0, b_ih0);
    for (int t = 0; t < Tq; t++) {
        stepA_kernel<<<128, NTHR>>>(w_hh0, b_hh0, t);
        stepB_kernel<<<128, NTHR>>>(w_ih1, w_hh1, b_ih1, b_hh1, t);
        stepC_kernel<<<128, NTHR>>>(b_fc, out, t);
    }
}

// round 5
// speedup vs baseline: 1.0149x; 1.0149x over previous
#include <cuda_runtime.h>
#include <math.h>

// Decoder free-run greedy decode. B=1024, T=64, V=256, LAT=256, H=512, L=2.
// fp32 via packed fma.rn.f32x2 (dual-FMA). Multi-launch, graph-capturable.
// Per step: A (GRU0), B1 (gi1 GEMM), B2 (GRU1), C (fc+argmax+onehot).
// RULE: __device__ symbols are referenced from DEVICE CODE ONLY (host-side
// references resolve to the host shadow variable -> garbage pointers).

#define Bq   1024
#define Hq   512
#define TH3  1536
#define Vq   256
#define LATq 256
#define Tq   64

typedef unsigned long long ull;

// ---------------- device scratch ------------------------------------------
__device__ float g_pre[Bq * TH3];          // latent part of gi0 (+b_ih0)
__device__ float g_gi1[Bq * TH3];          // per-step gi1 (+b_ih1)
__device__ float g_wvT[Vq * TH3];          // w_ih0 vocab cols, [v][gate3H]
__device__ float g_wfcT[Hq * Vq];          // w_fc transposed [k][v]
__device__ float g_h0[2][Bq * Hq];
__device__ float g_h1[2][Bq * Hq];
__device__ int   g_idx[Bq];

__device__ __forceinline__ float sigmoidf_(float x) {
    return 1.0f / (1.0f + expf(-x));
}
__device__ __forceinline__ ull fma2(ull a, ull b, ull c) {
    ull d;
    asm("fma.rn.f32x2 %0, %1, %2, %3;" : "=l"(d) : "l"(a), "l"(b), "l"(c));
    return d;
}
__device__ __forceinline__ void lds2(ull &x, ull &y, unsigned addr) {
    asm volatile("ld.shared.v2.b64 {%0,%1}, [%2];"
                 : "=l"(x), "=l"(y) : "r"(addr));
}
__device__ __forceinline__ float pairsum(ull p) {
    float lo, hi;
    asm("mov.b64 {%0,%1}, %2;" : "=f"(lo), "=f"(hi) : "l"(p));
    return lo + hi;
}

// ---------------- init: zero state + build transposes ---------------------
__global__ void __launch_bounds__(256) init_kernel(
    const float* __restrict__ w_ih0, const float* __restrict__ w_fc)
{
    const int gt = blockIdx.x * 256 + threadIdx.x;     // 0..32767
    float4 z = make_float4(0.f, 0.f, 0.f, 0.f);
    #pragma unroll
    for (int q = 0; q < 4; q++) {
        int i = gt + 32768 * q;
        reinterpret_cast<float4*>(g_h0[0])[i] = z;
        reinterpret_cast<float4*>(g_h1[0])[i] = z;
    }
    if (gt < Bq) g_idx[gt] = -1;
    #pragma unroll
    for (int q = 0; q < 12; q++) {                     // w_ih0 vocab transpose
        int i = gt + 32768 * q;
        int v = i / TH3, g = i - v * TH3;
        g_wvT[i] = w_ih0[g * 512 + 256 + v];
    }
    #pragma unroll
    for (int q = 0; q < 4; q++) {                      // w_fc transpose [k][v]
        int i = gt + 32768 * q;
        int k = i >> 8, v = i & 255;
        g_wfcT[i] = w_fc[v * 512 + k];
    }
}

// ---------------- packed-f32x2 GEMM core ----------------------------------
// acc[8][3] (k-even/odd packed pairs) += A[64 rows] @ Wslice^T
// Block: 512 threads = 64 colgroups (cg) x 8 rowgroups (rg).
// smem [row][k] pitch 32 floats, k-quad XOR-swizzled by (row&7).
__device__ __forceinline__ void gemm_core(
    ull acc[8][3],
    const float* __restrict__ A, int apitch, int rbase, int ktot,
    const float* __restrict__ W, int hs,
    float* sW, float* sH)
{
    const int tid = threadIdx.x;
    const int cg  = tid & 63;
    const int rg  = tid >> 6;
    const unsigned sWa = (unsigned)__cvta_generic_to_shared(sW);
    const unsigned sHa = (unsigned)__cvta_generic_to_shared(sH);
    const int csw = cg & 7;

    for (int k0 = 0; k0 < ktot; k0 += 32) {
        __syncthreads();
        // W panel: 192 rows x 32 k = 1536 float4, 3 per thread
        #pragma unroll
        for (int s = 0; s < 3; s++) {
            int item = tid + 512 * s;
            int row = item >> 3, kq = item & 7;
            int g = ((row >> 6) << 9) + hs * 64 + (row & 63);
            float4 v = *reinterpret_cast<const float4*>(
                &W[(size_t)g * 512 + k0 + 4 * kq]);
            *reinterpret_cast<float4*>(&sW[row * 32 + 4 * (kq ^ (row & 7))]) = v;
        }
        // A panel: 64 rows x 32 k = 512 float4, 1 per thread
        {
            int b = tid >> 3, kq = tid & 7;
            float4 v = *reinterpret_cast<const float4*>(
                &A[(size_t)(rbase + b) * apitch + k0 + 4 * kq]);
            *reinterpret_cast<float4*>(&sH[b * 32 + 4 * (kq ^ (b & 7))]) = v;
        }
        __syncthreads();
        #pragma unroll
        for (int q = 0; q < 8; q++) {
            ull w[3][2];
            #pragma unroll
            for (int j = 0; j < 3; j++) {
                unsigned adr = sWa + (((cg + 64 * j) * 32 + 4 * (q ^ csw)) << 2);
                lds2(w[j][0], w[j][1], adr);
            }
            #pragma unroll
            for (int i = 0; i < 8; i++) {
                ull a0, a1;
                unsigned adr = sHa + (((8 * rg + i) * 32 + 4 * (q ^ i)) << 2);
                lds2(a0, a1, adr);
                #pragma unroll
                for (int j = 0; j < 3; j++) {
                    acc[i][j] = fma2(a0, w[j][0], acc[i][j]);
                    acc[i][j] = fma2(a1, w[j][1], acc[i][j]);
                }
            }
        }
    }
}

// ---------------- gi kernel: out[b][g] = A @ W^T + bias -------------------
// MODE 0 (pre):  A = latent (ext ptr), ktot=256, out = g_pre
// MODE 1 (B1):   A = g_h0[1-(t&1)],    ktot=512, out = g_gi1
// All __device__ pointers resolved in device code.
template <int MODE>
__global__ void __launch_bounds__(512) gi_kernel(
    const float* __restrict__ Aext,
    const float* __restrict__ W, const float* __restrict__ bias, int t)
{
    __shared__ __align__(16) float sW[192 * 32];
    __shared__ __align__(16) float sH[64 * 32];
    const int tid = threadIdx.x;
    const int cg  = tid & 63;
    const int rg  = tid >> 6;
    const int bb  = blockIdx.x;
    const int hs  = bb & 7;
    const int rbase = (bb >> 3) * 64;
    const int hpos = hs * 64 + cg;

    const float* A    = (MODE == 0) ? Aext : g_h0[1 - (t & 1)];
    const int apitch  = (MODE == 0) ? LATq : Hq;
    const int ktot    = (MODE == 0) ? LATq : Hq;
    float* outbuf     = (MODE == 0) ? g_pre : g_gi1;

    ull acc[8][3];
    #pragma unroll
    for (int i = 0; i < 8; i++)
        #pragma unroll
        for (int j = 0; j < 3; j++) acc[i][j] = 0ULL;
    gemm_core(acc, A, apitch, rbase, ktot, W, hs, sW, sH);

    float b0 = bias[hpos], b1 = bias[512 + hpos], b2 = bias[1024 + hpos];
    #pragma unroll
    for (int i = 0; i < 8; i++) {
        int b = rbase + 8 * rg + i;
        outbuf[(size_t)b * TH3 + hpos]        = pairsum(acc[i][0]) + b0;
        outbuf[(size_t)b * TH3 + 512 + hpos]  = pairsum(acc[i][1]) + b1;
        outbuf[(size_t)b * TH3 + 1024 + hpos] = pairsum(acc[i][2]) + b2;
    }
}

// ---------------- stage A: layer-0 GRU (with one-hot gather) --------------
__global__ void __launch_bounds__(512) stepA_kernel(
    const float* __restrict__ w_hh0, const float* __restrict__ b_hh0, int t)
{
    __shared__ __align__(16) float sW[192 * 32];
    __shared__ __align__(16) float sH[64 * 32];
    const int pr = t & 1, pw = 1 - pr;
    const int tid = threadIdx.x;
    const int cg  = tid & 63;
    const int rg  = tid >> 6;
    const int bb  = blockIdx.x;
    const int hs  = bb & 7;
    const int rbase = (bb >> 3) * 64;
    const int hpos = hs * 64 + cg;

    ull acc[8][3];
    #pragma unroll
    for (int i = 0; i < 8; i++)
        #pragma unroll
        for (int j = 0; j < 3; j++) acc[i][j] = 0ULL;
    gemm_core(acc, g_h0[pr], Hq, rbase, Hq, w_hh0, hs, sW, sH);

    float bhR = b_hh0[hpos], bhZ = b_hh0[512 + hpos], bhN = b_hh0[1024 + hpos];
    #pragma unroll
    for (int i = 0; i < 8; i++) {
        int b  = rbase + 8 * rg + i;
        int ix = g_idx[b];
        float ir  = g_pre[(size_t)b * TH3 + hpos];
        float iz  = g_pre[(size_t)b * TH3 + 512 + hpos];
        float in_ = g_pre[(size_t)b * TH3 + 1024 + hpos];
        if (ix >= 0) {
            ir  += g_wvT[(size_t)ix * TH3 + hpos];
            iz  += g_wvT[(size_t)ix * TH3 + 512 + hpos];
            in_ += g_wvT[(size_t)ix * TH3 + 1024 + hpos];
        }
        float r = sigmoidf_(ir + pairsum(acc[i][0]) + bhR);
        float z = sigmoidf_(iz + pairsum(acc[i][1]) + bhZ);
        float n = tanhf(in_ + r * (pairsum(acc[i][2]) + bhN));
        float hold = g_h0[pr][(size_t)b * Hq + hpos];
        g_h0[pw][(size_t)b * Hq + hpos] = (1.f - z) * n + z * hold;
    }
}

// ---------------- stage B2: layer-1 GRU (gi1 precomputed) -----------------
__global__ void __launch_bounds__(512) stepB2_kernel(
    const float* __restrict__ w_hh1, const float* __restrict__ b_hh1, int t)
{
    __shared__ __align__(16) float sW[192 * 32];
    __shared__ __align__(16) float sH[64 * 32];
    const int pr = t & 1, pw = 1 - pr;
    const int tid = threadIdx.x;
    const int cg  = tid & 63;
    const int rg  = tid >> 6;
    const int bb  = blockIdx.x;
    const int hs  = bb & 7;
    const int rbase = (bb >> 3) * 64;
    const int hpos = hs * 64 + cg;

    ull acc[8][3];
    #pragma unroll
    for (int i = 0; i < 8; i++)
        #pragma unroll
        for (int j = 0; j < 3; j++) acc[i][j] = 0ULL;
    gemm_core(acc, g_h1[pr], Hq, rbase, Hq, w_hh1, hs, sW, sH);

    float bhR = b_hh1[hpos], bhZ = b_hh1[512 + hpos], bhN = b_hh1[1024 + hpos];
    #pragma unroll
    for (int i = 0; i < 8; i++) {
        int b = rbase + 8 * rg + i;
        float ir  = g_gi1[(size_t)b * TH3 + hpos];
        float iz  = g_gi1[(size_t)b * TH3 + 512 + hpos];
        float in_ = g_gi1[(size_t)b * TH3 + 1024 + hpos];
        float r = sigmoidf_(ir + pairsum(acc[i][0]) + bhR);
        float z = sigmoidf_(iz + pairsum(acc[i][1]) + bhZ);
        float n = tanhf(in_ + r * (pairsum(acc[i][2]) + bhN));
        float hold = g_h1[pr][(size_t)b * Hq + hpos];
        g_h1[pw][(size_t)b * Hq + hpos] = (1.f - z) * n + z * hold;
    }
}

// ---------------- stage C: logits + argmax + one-hot ----------------------
__global__ void __launch_bounds__(256) stepC_kernel(
    const float* __restrict__ b_fc, float* __restrict__ out, int t)
{
    __shared__ float sHL[8 * Hq];
    __shared__ float sLOG[8 * Vq];
    __shared__ int   sIDX[8];
    const int pw = 1 - (t & 1);
    const int tid = threadIdx.x;
    const int tx  = tid & 31;
    const int ty  = tid >> 5;
    const int rb  = blockIdx.x * 8;

    #pragma unroll
    for (int q = 0; q < 4; q++) {
        int f4 = tid + 256 * q;
        int r  = f4 >> 7;
        int kq = f4 & 127;
        float4 v = *reinterpret_cast<const float4*>(
            &g_h1[pw][(size_t)(rb + r) * Hq + 4 * kq]);
        *reinterpret_cast<float4*>(&sHL[r * Hq + 4 * kq]) = v;
    }
    __syncthreads();

    float acc[8];
    #pragma unroll
    for (int r = 0; r < 8; r++) acc[r] = 0.f;
    #pragma unroll 8
    for (int k = 0; k < Hq; k++) {
        float wv = g_wfcT[k * Vq + tid];
        #pragma unroll
        for (int r = 0; r < 8; r++) acc[r] += sHL[r * Hq + k] * wv;
    }
    float bf = b_fc[tid];
    #pragma unroll
    for (int r = 0; r < 8; r++) sLOG[r * Vq + tid] = acc[r] + bf;
    __syncthreads();

    {   // warp ty reduces row ty, first-max tie-break (matches jnp.argmax)
        int row = ty;
        float bv = -3.4e38f;
        int   bi = 0;
        #pragma unroll
        for (int m = 0; m < 8; m++) {
            int idx = tx + 32 * m;
            float v = sLOG[row * Vq + idx];
            if (v > bv) { bv = v; bi = idx; }
        }
        #pragma unroll
        for (int off = 16; off > 0; off >>= 1) {
            float ov = __shfl_down_sync(0xffffffffu, bv, off);
            int   oi = __shfl_down_sync(0xffffffffu, bi, off);
            if (ov > bv || (ov == bv && oi < bi)) { bv = ov; bi = oi; }
        }
        if (tx == 0) sIDX[row] = bi;
    }
    __syncthreads();
    #pragma unroll
    for (int r = 0; r < 8; r++) {
        out[(size_t)(rb + r) * (Tq * Vq) + t * Vq + tid] =
            (tid == sIDX[r]) ? 1.0f : 0.0f;
    }
    if (tid < 8) g_idx[rb + tid] = sIDX[tid];
}

// ---------------- launch ---------------------------------------------------
extern "C" void kernel_launch(void* const* d_in, const int* in_sizes, int n_in,
                              void* d_out, int out_size)
{
    const float* latent = (const float*)d_in[0];
    // d_in[1] enthalpy: unused on freerun path
    const float* w_ih0  = (const float*)d_in[2];
    const float* w_hh0  = (const float*)d_in[3];
    const float* b_ih0  = (const float*)d_in[4];
    const float* b_hh0  = (const float*)d_in[5];
    const float* w_ih1  = (const float*)d_in[6];
    const float* w_hh1  = (const float*)d_in[7];
    const float* b_ih1  = (const float*)d_in[8];
    const float* b_hh1  = (const float*)d_in[9];
    const float* w_fc   = (const float*)d_in[10];
    const float* b_fc   = (const float*)d_in[11];
    float* out = (float*)d_out;

    init_kernel<<<128, 256>>>(w_ih0, w_fc);
    gi_kernel<0><<<128, 512>>>(latent, w_ih0, b_ih0, 0);   // -> g_pre
    for (int t = 0; t < Tq; t++) {
        stepA_kernel<<<128, 512>>>(w_hh0, b_hh0, t);
        gi_kernel<1><<<128, 512>>>(nullptr, w_ih1, b_ih1, t);  // -> g_gi1
        stepB2_kernel<<<128, 512>>>(w_hh1, b_hh1, t);
        stepC_kernel<<<128, 256>>>(b_fc, out, t);
    }
}